// round 11
// baseline (speedup 1.0000x reference)
#include <cuda_runtime.h>

// x: (32, 1, 1024, 1024) fp32. out same shape.
#define IMG_N  32
#define HDIM   1024
#define WDIM   1024
#define RSTRIP 16                        // rows per block strip
#define STRIPS 64                        // strips per image
#define IMGS_PER_CHUNK 4
#define CHUNKS (IMG_N / IMGS_PER_CHUNK)  // 8
#define CBLOCKS (IMGS_PER_CHUNK * STRIPS)// 256 blocks per chunk-kernel
#define RING   6                         // rows in flight (distance-3 pipeline)

// Per-block partials, indexed by absolute (chunk, block). Written before read.
__device__ double g_psum[CHUNKS * CBLOCKS];
__device__ double g_pss [CHUNKS * CBLOCKS];

// ---------------------------------------------------------------- loads/halo
// LU: use last-use loads (pass2: line is dead after this read, free L2 early).
template<bool INTERIOR, bool LU>
__device__ __forceinline__ void load_row_t(const float* __restrict__ base, int row,
                                           int col, int lane,
                                           float4& v, float& el, float& er) {
    if (!INTERIOR) {
        if (row < 0 || row >= HDIM) {
            v = make_float4(0.f, 0.f, 0.f, 0.f); el = 0.f; er = 0.f; return;
        }
    }
    const float* p = base + (size_t)row * WDIM;
    if (LU) v = __ldlu((const float4*)(p + col));
    else    v = *(const float4*)(p + col);
    el = 0.f; er = 0.f;
    if (lane == 0  && col > 0)        el = __ldg(p + col - 1);
    if (lane == 31 && col + 4 < WDIM) er = __ldg(p + col + 4);
}

__device__ __forceinline__ void make_halo(const float4& v, float el, float er,
                                          int lane, float& l, float& r) {
    float lu = __shfl_up_sync(0xffffffffu,  v.w, 1);
    float rd = __shfl_down_sync(0xffffffffu, v.x, 1);
    l = (lane == 0)  ? el : lu;
    r = (lane == 31) ? er : rd;
}

// z = center - (L + 2*DL + 4*D + 8*DR + 16*R + 32*UR + 64*U + 128*UL)/255
// u = row-1, d = row+1 (reference offsets; zero padding outside).
__device__ __forceinline__ void stencil4(const float4& u, float ul, float ur,
                                         const float4& c, float cl, float cr,
                                         const float4& d, float dl, float dr,
                                         float z[4]) {
    const float INV255 = 1.0f / 255.0f;
    z[0] = c.x - (cl  + 2.f*dl  + 4.f*d.x + 8.f*d.y + 16.f*c.y + 32.f*u.y + 64.f*u.x + 128.f*ul ) * INV255;
    z[1] = c.y - (c.x + 2.f*d.x + 4.f*d.y + 8.f*d.z + 16.f*c.z + 32.f*u.z + 64.f*u.y + 128.f*u.x) * INV255;
    z[2] = c.z - (c.y + 2.f*d.y + 4.f*d.z + 8.f*d.w + 16.f*c.w + 32.f*u.w + 64.f*u.z + 128.f*u.y) * INV255;
    z[3] = c.w - (c.z + 2.f*d.z + 4.f*d.w + 8.f*dr  + 16.f*cr  + 32.f*ur  + 64.f*u.w + 128.f*u.z) * INV255;
}

// ================= Pass 1 (per chunk): stats over each 16-row strip =========
template<bool INTERIOR>
__device__ __forceinline__ void pass1_strip(const float* __restrict__ base,
                                            int r0, int col, int lane,
                                            float& s, float& ss) {
    float4 v[RING]; float el[RING], er[RING], l[RING], r[RING];
    #pragma unroll
    for (int k = 0; k < RING - 1; k++)            // abs rows r0-1 .. r0+3
        load_row_t<INTERIOR, false>(base, r0 - 1 + k, col, lane, v[k], el[k], er[k]);
    make_halo(v[0], el[0], er[0], lane, l[0], r[0]);
    make_halo(v[1], el[1], er[1], lane, l[1], r[1]);

    s = 0.f; ss = 0.f;
    #pragma unroll
    for (int i = 0; i < RSTRIP; i++) {
        if (i < RSTRIP - 3) {                     // load abs row r0+i+4
            const int rel = (i + RING - 1) % RING;
            load_row_t<INTERIOR, false>(base, r0 + i + 4, col, lane, v[rel], el[rel], er[rel]);
        }
        const int a = i % RING, b = (i + 1) % RING, c = (i + 2) % RING;
        make_halo(v[c], el[c], er[c], lane, l[c], r[c]);
        float z[4];
        stencil4(v[a], l[a], r[a], v[b], l[b], r[b], v[c], l[c], r[c], z);
        s  += (z[0] + z[1]) + (z[2] + z[3]);
        ss += (z[0]*z[0] + z[1]*z[1]) + (z[2]*z[2] + z[3]*z[3]);
    }
}

__global__ void __launch_bounds__(256) ltpe_pass1(const float* __restrict__ x, int chunk) {
    int strip  = blockIdx.x & (STRIPS - 1);
    int imgblk = blockIdx.x >> 6;                 // 0..3
    int img    = chunk * IMGS_PER_CHUNK + imgblk;
    int r0     = strip * RSTRIP;
    const float* base = x + (size_t)img * HDIM * WDIM;
    int col  = threadIdx.x * 4;
    int lane = threadIdx.x & 31;

    float s, ss;
    if (strip != 0 && strip != STRIPS - 1) pass1_strip<true >(base, r0, col, lane, s, ss);
    else                                   pass1_strip<false>(base, r0, col, lane, s, ss);

    #pragma unroll
    for (int o = 16; o > 0; o >>= 1) {
        s  += __shfl_xor_sync(0xffffffffu, s,  o);
        ss += __shfl_xor_sync(0xffffffffu, ss, o);
    }
    __shared__ float ws[8], wss[8];
    int wid = threadIdx.x >> 5;
    if (lane == 0) { ws[wid] = s; wss[wid] = ss; }
    __syncthreads();
    if (threadIdx.x == 0) {
        float S = 0.f, SS = 0.f;
        #pragma unroll
        for (int i = 0; i < 8; i++) { S += ws[i]; SS += wss[i]; }
        g_psum[chunk * CBLOCKS + blockIdx.x] = (double)S;
        g_pss [chunk * CBLOCKS + blockIdx.x] = (double)SS;
    }
}

// ================= Pass 2 (per chunk): normalize + stream out ===============
template<bool INTERIOR>
__device__ __forceinline__ void pass2_strip(const float* __restrict__ base,
                                            float* __restrict__ obase,
                                            int r0, int col, int lane, int pbase) {
    float4 v[RING]; float el[RING], er[RING], l[RING], r[RING];
    // Pixel preloads FIRST so the (L2-hot) reads overlap the stats reduce.
    #pragma unroll
    for (int k = 0; k < RING - 1; k++)
        load_row_t<INTERIOR, true>(base, r0 - 1 + k, col, lane, v[k], el[k], er[k]);

    // Fixed-order stats reduction over my image's 64 partials (deterministic).
    __shared__ double rs[STRIPS], rss[STRIPS];
    __shared__ float s_mean, s_inv;
    if (threadIdx.x < STRIPS) {
        rs[threadIdx.x]  = g_psum[pbase + threadIdx.x];
        rss[threadIdx.x] = g_pss [pbase + threadIdx.x];
    }
    __syncthreads();
    #pragma unroll
    for (int o = STRIPS / 2; o > 0; o >>= 1) {
        if (threadIdx.x < o) {
            rs[threadIdx.x]  += rs[threadIdx.x + o];
            rss[threadIdx.x] += rss[threadIdx.x + o];
        }
        __syncthreads();
    }
    if (threadIdx.x == 0) {
        const double N = (double)HDIM * WDIM;
        double mm  = rs[0] / N;
        double var = rss[0] / N - mm * mm;
        s_mean = (float)mm;
        // o = 0.5*z + 0.5 with IN eps=1e-5  =>  normalize z with eps' = 4e-5
        s_inv = (float)rsqrt(var + 4e-5);
    }
    __syncthreads();
    const float m = s_mean, inv = s_inv;

    make_halo(v[0], el[0], er[0], lane, l[0], r[0]);
    make_halo(v[1], el[1], er[1], lane, l[1], r[1]);

    #pragma unroll
    for (int i = 0; i < RSTRIP; i++) {
        if (i < RSTRIP - 3) {
            const int rel = (i + RING - 1) % RING;
            load_row_t<INTERIOR, true>(base, r0 + i + 4, col, lane, v[rel], el[rel], er[rel]);
        }
        const int a = i % RING, b = (i + 1) % RING, c = (i + 2) % RING;
        make_halo(v[c], el[c], er[c], lane, l[c], r[c]);
        float z[4];
        stencil4(v[a], l[a], r[a], v[b], l[b], r[b], v[c], l[c], r[c], z);
        float4 o;
        o.x = (z[0] - m) * inv;
        o.y = (z[1] - m) * inv;
        o.z = (z[2] - m) * inv;
        o.w = (z[3] - m) * inv;
        // Evict-first store: output is never re-read; don't displace x in L2.
        __stcs((float4*)(obase + (size_t)(r0 + i) * WDIM + col), o);
    }
}

__global__ void __launch_bounds__(256) ltpe_pass2(const float* __restrict__ x,
                                                  float* __restrict__ out, int chunk) {
    int strip  = blockIdx.x & (STRIPS - 1);
    int imgblk = blockIdx.x >> 6;
    int img    = chunk * IMGS_PER_CHUNK + imgblk;
    int r0     = strip * RSTRIP;
    const float* base  = x   + (size_t)img * HDIM * WDIM;
    float*       obase = out + (size_t)img * HDIM * WDIM;
    int col  = threadIdx.x * 4;
    int lane = threadIdx.x & 31;
    int pbase = chunk * CBLOCKS + imgblk * STRIPS;

    if (strip != 0 && strip != STRIPS - 1) pass2_strip<true >(base, obase, r0, col, lane, pbase);
    else                                   pass2_strip<false>(base, obase, r0, col, lane, pbase);
}

// ------------------------------------------------------------------ launch
// Software pipeline across two streams (fork-join inside graph capture):
//   S0 (capture/default): p1(c0) e0 p1(c1) e1 ... p1(c7) e7 ... wait(join)
//   S1:                   wait(e0) p2(c0) wait(e1) p2(c1) ... p2(c7) rec(join)
// p2(c) reads x-chunk c right after p1(c) loaded it -> L2-resident (16MB/chunk
// vs 126MB L2). No device-side sync anywhere; worst case is a clean capture
// error, never a hang.
extern "C" void kernel_launch(void* const* d_in, const int* in_sizes, int n_in,
                              void* d_out, int out_size) {
    const float* x   = (const float*)d_in[0];
    float*       out = (float*)d_out;

    // One-time creation of the side stream + events (host objects, no device
    // memory). The first (uncaptured) correctness call performs this; captured
    // calls then replay an identical launch/event sequence every time.
    static cudaStream_t s1 = nullptr;
    static cudaEvent_t  ev[CHUNKS];
    static cudaEvent_t  evj = nullptr;
    if (s1 == nullptr) {
        cudaStreamCreateWithFlags(&s1, cudaStreamNonBlocking);
        for (int c = 0; c < CHUNKS; c++)
            cudaEventCreateWithFlags(&ev[c], cudaEventDisableTiming);
        cudaEventCreateWithFlags(&evj, cudaEventDisableTiming);
    }

    for (int c = 0; c < CHUNKS; c++) {
        ltpe_pass1<<<CBLOCKS, 256>>>(x, c);
        cudaEventRecord(ev[c], 0);                 // after p1(c) on default stream
        cudaStreamWaitEvent(s1, ev[c], 0);         // p2(c) waits only on p1(c)
        ltpe_pass2<<<CBLOCKS, 256, 0, s1>>>(x, out, c);
    }
    cudaEventRecord(evj, s1);                      // join S1 back into S0
    cudaStreamWaitEvent(0, evj, 0);
}

// round 12
// speedup vs baseline: 1.1657x; 1.1657x over previous
#include <cuda_runtime.h>

// x: (32, 1, 1024, 1024) fp32. out same shape.
#define IMG_N  32
#define HDIM   1024
#define WDIM   1024
#define RSTRIP 16                        // rows per block strip
#define STRIPS 64                        // strips per image
#define IMGS_PER_CHUNK 8
#define CHUNKS (IMG_N / IMGS_PER_CHUNK)  // 4
#define CBLOCKS (IMGS_PER_CHUNK * STRIPS)// 512 blocks per chunk-kernel
#define RING   6                         // rows in flight (distance-3 pipeline)

// Per-block partials, indexed by absolute (chunk, block). Written before read.
__device__ double g_psum[CHUNKS * CBLOCKS];
__device__ double g_pss [CHUNKS * CBLOCKS];

// ---------------------------------------------------------------- loads/halo
// LU: last-use loads (pass2: line is dead after this read, free L2 early).
template<bool INTERIOR, bool LU>
__device__ __forceinline__ void load_row_t(const float* __restrict__ base, int row,
                                           int col, int lane,
                                           float4& v, float& el, float& er) {
    if (!INTERIOR) {
        if (row < 0 || row >= HDIM) {
            v = make_float4(0.f, 0.f, 0.f, 0.f); el = 0.f; er = 0.f; return;
        }
    }
    const float* p = base + (size_t)row * WDIM;
    if (LU) v = __ldlu((const float4*)(p + col));
    else    v = *(const float4*)(p + col);
    el = 0.f; er = 0.f;
    if (lane == 0  && col > 0)        el = __ldg(p + col - 1);
    if (lane == 31 && col + 4 < WDIM) er = __ldg(p + col + 4);
}

__device__ __forceinline__ void make_halo(const float4& v, float el, float er,
                                          int lane, float& l, float& r) {
    float lu = __shfl_up_sync(0xffffffffu,  v.w, 1);
    float rd = __shfl_down_sync(0xffffffffu, v.x, 1);
    l = (lane == 0)  ? el : lu;
    r = (lane == 31) ? er : rd;
}

// z = center - (L + 2*DL + 4*D + 8*DR + 16*R + 32*UR + 64*U + 128*UL)/255
// u = row-1, d = row+1 (reference offsets; zero padding outside).
__device__ __forceinline__ void stencil4(const float4& u, float ul, float ur,
                                         const float4& c, float cl, float cr,
                                         const float4& d, float dl, float dr,
                                         float z[4]) {
    const float INV255 = 1.0f / 255.0f;
    z[0] = c.x - (cl  + 2.f*dl  + 4.f*d.x + 8.f*d.y + 16.f*c.y + 32.f*u.y + 64.f*u.x + 128.f*ul ) * INV255;
    z[1] = c.y - (c.x + 2.f*d.x + 4.f*d.y + 8.f*d.z + 16.f*c.z + 32.f*u.z + 64.f*u.y + 128.f*u.x) * INV255;
    z[2] = c.z - (c.y + 2.f*d.y + 4.f*d.z + 8.f*d.w + 16.f*c.w + 32.f*u.w + 64.f*u.z + 128.f*u.y) * INV255;
    z[3] = c.w - (c.z + 2.f*d.z + 4.f*d.w + 8.f*dr  + 16.f*cr  + 32.f*ur  + 64.f*u.w + 128.f*u.z) * INV255;
}

// ================= Pass 1 (per chunk): stats over each 16-row strip =========
template<bool INTERIOR>
__device__ __forceinline__ void pass1_strip(const float* __restrict__ base,
                                            int r0, int col, int lane,
                                            float& s, float& ss) {
    float4 v[RING]; float el[RING], er[RING], l[RING], r[RING];
    #pragma unroll
    for (int k = 0; k < RING - 1; k++)            // abs rows r0-1 .. r0+3
        load_row_t<INTERIOR, false>(base, r0 - 1 + k, col, lane, v[k], el[k], er[k]);
    make_halo(v[0], el[0], er[0], lane, l[0], r[0]);
    make_halo(v[1], el[1], er[1], lane, l[1], r[1]);

    s = 0.f; ss = 0.f;
    #pragma unroll
    for (int i = 0; i < RSTRIP; i++) {
        if (i < RSTRIP - 3) {                     // load abs row r0+i+4
            const int rel = (i + RING - 1) % RING;
            load_row_t<INTERIOR, false>(base, r0 + i + 4, col, lane, v[rel], el[rel], er[rel]);
        }
        const int a = i % RING, b = (i + 1) % RING, c = (i + 2) % RING;
        make_halo(v[c], el[c], er[c], lane, l[c], r[c]);
        float z[4];
        stencil4(v[a], l[a], r[a], v[b], l[b], r[b], v[c], l[c], r[c], z);
        s  += (z[0] + z[1]) + (z[2] + z[3]);
        ss += (z[0]*z[0] + z[1]*z[1]) + (z[2]*z[2] + z[3]*z[3]);
    }
}

__global__ void __launch_bounds__(256) ltpe_pass1(const float* __restrict__ x, int chunk) {
    int strip  = blockIdx.x & (STRIPS - 1);
    int imgblk = blockIdx.x >> 6;                 // 0..7
    int img    = chunk * IMGS_PER_CHUNK + imgblk;
    int r0     = strip * RSTRIP;
    const float* base = x + (size_t)img * HDIM * WDIM;
    int col  = threadIdx.x * 4;
    int lane = threadIdx.x & 31;

    float s, ss;
    if (strip != 0 && strip != STRIPS - 1) pass1_strip<true >(base, r0, col, lane, s, ss);
    else                                   pass1_strip<false>(base, r0, col, lane, s, ss);

    #pragma unroll
    for (int o = 16; o > 0; o >>= 1) {
        s  += __shfl_xor_sync(0xffffffffu, s,  o);
        ss += __shfl_xor_sync(0xffffffffu, ss, o);
    }
    __shared__ float ws[8], wss[8];
    int wid = threadIdx.x >> 5;
    if (lane == 0) { ws[wid] = s; wss[wid] = ss; }
    __syncthreads();
    if (threadIdx.x == 0) {
        float S = 0.f, SS = 0.f;
        #pragma unroll
        for (int i = 0; i < 8; i++) { S += ws[i]; SS += wss[i]; }
        g_psum[chunk * CBLOCKS + blockIdx.x] = (double)S;
        g_pss [chunk * CBLOCKS + blockIdx.x] = (double)SS;
    }
}

// ================= Pass 2 (per chunk): normalize + stream out ===============
template<bool INTERIOR>
__device__ __forceinline__ void pass2_strip(const float* __restrict__ base,
                                            float* __restrict__ obase,
                                            int r0, int col, int lane, int pbase) {
    float4 v[RING]; float el[RING], er[RING], l[RING], r[RING];
    // Pixel preloads FIRST so the (L2-hot) reads overlap the stats reduce.
    #pragma unroll
    for (int k = 0; k < RING - 1; k++)
        load_row_t<INTERIOR, true>(base, r0 - 1 + k, col, lane, v[k], el[k], er[k]);

    // Fixed-order stats reduction over my image's 64 partials (deterministic).
    __shared__ double rs[STRIPS], rss[STRIPS];
    __shared__ float s_mean, s_inv;
    if (threadIdx.x < STRIPS) {
        rs[threadIdx.x]  = g_psum[pbase + threadIdx.x];
        rss[threadIdx.x] = g_pss [pbase + threadIdx.x];
    }
    __syncthreads();
    #pragma unroll
    for (int o = STRIPS / 2; o > 0; o >>= 1) {
        if (threadIdx.x < o) {
            rs[threadIdx.x]  += rs[threadIdx.x + o];
            rss[threadIdx.x] += rss[threadIdx.x + o];
        }
        __syncthreads();
    }
    if (threadIdx.x == 0) {
        const double N = (double)HDIM * WDIM;
        double mm  = rs[0] / N;
        double var = rss[0] / N - mm * mm;
        s_mean = (float)mm;
        // o = 0.5*z + 0.5 with IN eps=1e-5  =>  normalize z with eps' = 4e-5
        s_inv = (float)rsqrt(var + 4e-5);
    }
    __syncthreads();
    const float m = s_mean, inv = s_inv;

    make_halo(v[0], el[0], er[0], lane, l[0], r[0]);
    make_halo(v[1], el[1], er[1], lane, l[1], r[1]);

    #pragma unroll
    for (int i = 0; i < RSTRIP; i++) {
        if (i < RSTRIP - 3) {
            const int rel = (i + RING - 1) % RING;
            load_row_t<INTERIOR, true>(base, r0 + i + 4, col, lane, v[rel], el[rel], er[rel]);
        }
        const int a = i % RING, b = (i + 1) % RING, c = (i + 2) % RING;
        make_halo(v[c], el[c], er[c], lane, l[c], r[c]);
        float z[4];
        stencil4(v[a], l[a], r[a], v[b], l[b], r[b], v[c], l[c], r[c], z);
        float4 o;
        o.x = (z[0] - m) * inv;
        o.y = (z[1] - m) * inv;
        o.z = (z[2] - m) * inv;
        o.w = (z[3] - m) * inv;
        // Evict-first store: output is never re-read; don't displace x in L2.
        __stcs((float4*)(obase + (size_t)(r0 + i) * WDIM + col), o);
    }
}

__global__ void __launch_bounds__(256) ltpe_pass2(const float* __restrict__ x,
                                                  float* __restrict__ out, int chunk) {
    int strip  = blockIdx.x & (STRIPS - 1);
    int imgblk = blockIdx.x >> 6;
    int img    = chunk * IMGS_PER_CHUNK + imgblk;
    int r0     = strip * RSTRIP;
    const float* base  = x   + (size_t)img * HDIM * WDIM;
    float*       obase = out + (size_t)img * HDIM * WDIM;
    int col  = threadIdx.x * 4;
    int lane = threadIdx.x & 31;
    int pbase = chunk * CBLOCKS + imgblk * STRIPS;

    if (strip != 0 && strip != STRIPS - 1) pass2_strip<true >(base, obase, r0, col, lane, pbase);
    else                                   pass2_strip<false>(base, obase, r0, col, lane, pbase);
}

// ------------------------------------------------------------------ launch
// Software pipeline across two streams (fork-join inside graph capture):
//   S0: p1(c0) e0 p1(c1) e1 p1(c2) e2 p1(c3) e3 ... wait(join)
//   S1: wait(e0) p2(c0) wait(e1) p2(c1) ... p2(c3) rec(join)
// 512-block kernels (3.46 blocks/SM) restore the ~28 warps/SM at which these
// kernel bodies demonstrably reach ~60% DRAM (R7). p2(c) reads x-chunk c that
// p1(c) just streamed -> L2-resident (32MB/chunk; c + c+1 fit in 126MB L2).
// No device-side sync anywhere — worst case is a clean error, never a hang.
extern "C" void kernel_launch(void* const* d_in, const int* in_sizes, int n_in,
                              void* d_out, int out_size) {
    const float* x   = (const float*)d_in[0];
    float*       out = (float*)d_out;

    // One-time host-object creation (no device memory). First (uncaptured)
    // correctness call creates them; captured calls replay identical sequence.
    static cudaStream_t s1 = nullptr;
    static cudaEvent_t  ev[CHUNKS];
    static cudaEvent_t  evj = nullptr;
    if (s1 == nullptr) {
        cudaStreamCreateWithFlags(&s1, cudaStreamNonBlocking);
        for (int c = 0; c < CHUNKS; c++)
            cudaEventCreateWithFlags(&ev[c], cudaEventDisableTiming);
        cudaEventCreateWithFlags(&evj, cudaEventDisableTiming);
    }

    for (int c = 0; c < CHUNKS; c++) {
        ltpe_pass1<<<CBLOCKS, 256>>>(x, c);
        cudaEventRecord(ev[c], 0);                 // after p1(c) on default stream
        cudaStreamWaitEvent(s1, ev[c], 0);         // p2(c) waits only on p1(c)
        ltpe_pass2<<<CBLOCKS, 256, 0, s1>>>(x, out, c);
    }
    cudaEventRecord(evj, s1);                      // join S1 back into S0
    cudaStreamWaitEvent(0, evj, 0);
}

// round 13
// speedup vs baseline: 1.3119x; 1.1254x over previous
#include <cuda_runtime.h>
#include <cuda_fp16.h>

// x: (32, 1, 1024, 1024) fp32. out same shape.
#define IMG_N  32
#define HDIM   1024
#define WDIM   1024
#define RSTRIP 16                      // rows per block strip
#define STRIPS (HDIM / RSTRIP)         // 64 strips per image
#define NBLOCKS (IMG_N * STRIPS)       // 2048 blocks per pass
#define RING   6                       // rows in flight (distance-3 pipeline)

// Per-block partial sums (written unconditionally by pass1 -> no zeroing).
__device__ double g_psum[NBLOCKS];
__device__ double g_pss[NBLOCKS];
// fp16 z scratch (64MB). Static __device__ array = the sanctioned scratch path.
__device__ __half g_z[(size_t)IMG_N * HDIM * WDIM];

// ---------------------------------------------------------------- loads/halo
template<bool INTERIOR>
__device__ __forceinline__ void load_row_t(const float* __restrict__ base, int row,
                                           int col, int lane,
                                           float4& v, float& el, float& er) {
    if (!INTERIOR) {
        if (row < 0 || row >= HDIM) {
            v = make_float4(0.f, 0.f, 0.f, 0.f); el = 0.f; er = 0.f; return;
        }
    }
    const float* p = base + (size_t)row * WDIM;
    // Streamed read: x is never re-read after pass1; don't displace z in L2.
    v = __ldcs((const float4*)(p + col));
    el = 0.f; er = 0.f;
    if (lane == 0  && col > 0)        el = __ldg(p + col - 1);
    if (lane == 31 && col + 4 < WDIM) er = __ldg(p + col + 4);
}

__device__ __forceinline__ void make_halo(const float4& v, float el, float er,
                                          int lane, float& l, float& r) {
    float lu = __shfl_up_sync(0xffffffffu,  v.w, 1);
    float rd = __shfl_down_sync(0xffffffffu, v.x, 1);
    l = (lane == 0)  ? el : lu;
    r = (lane == 31) ? er : rd;
}

// z = center - (L + 2*DL + 4*D + 8*DR + 16*R + 32*UR + 64*U + 128*UL)/255
// u = row-1, d = row+1 (reference offsets; zero padding outside).
__device__ __forceinline__ void stencil4(const float4& u, float ul, float ur,
                                         const float4& c, float cl, float cr,
                                         const float4& d, float dl, float dr,
                                         float z[4]) {
    const float INV255 = 1.0f / 255.0f;
    z[0] = c.x - (cl  + 2.f*dl  + 4.f*d.x + 8.f*d.y + 16.f*c.y + 32.f*u.y + 64.f*u.x + 128.f*ul ) * INV255;
    z[1] = c.y - (c.x + 2.f*d.x + 4.f*d.y + 8.f*d.z + 16.f*c.z + 32.f*u.z + 64.f*u.y + 128.f*u.x) * INV255;
    z[2] = c.z - (c.y + 2.f*d.y + 4.f*d.z + 8.f*d.w + 16.f*c.w + 32.f*u.w + 64.f*u.z + 128.f*u.y) * INV255;
    z[3] = c.w - (c.z + 2.f*d.z + 4.f*d.w + 8.f*dr  + 16.f*cr  + 32.f*ur  + 64.f*u.w + 128.f*u.z) * INV255;
}

// ============ Pass 1: stencil -> z(fp16) + stats over each 16-row strip ======
// Ring of RING=6 rows, distance-3 pipeline (proven R7 body) + fp16 z store.
template<bool INTERIOR>
__device__ __forceinline__ void pass1_strip(const float* __restrict__ base,
                                            __half* __restrict__ zb,
                                            int r0, int col, int lane,
                                            float& s, float& ss) {
    float4 v[RING]; float el[RING], er[RING], l[RING], r[RING];
    #pragma unroll
    for (int k = 0; k < RING - 1; k++)            // abs rows r0-1 .. r0+3
        load_row_t<INTERIOR>(base, r0 - 1 + k, col, lane, v[k], el[k], er[k]);
    make_halo(v[0], el[0], er[0], lane, l[0], r[0]);
    make_halo(v[1], el[1], er[1], lane, l[1], r[1]);

    s = 0.f; ss = 0.f;
    #pragma unroll
    for (int i = 0; i < RSTRIP; i++) {
        if (i < RSTRIP - 3) {                     // load abs row r0+i+4
            const int rel = (i + RING - 1) % RING;
            load_row_t<INTERIOR>(base, r0 + i + 4, col, lane, v[rel], el[rel], er[rel]);
        }
        const int a = i % RING, b = (i + 1) % RING, c = (i + 2) % RING;
        make_halo(v[c], el[c], er[c], lane, l[c], r[c]);
        float z[4];
        stencil4(v[a], l[a], r[a], v[b], l[b], r[b], v[c], l[c], r[c], z);
        s  += (z[0] + z[1]) + (z[2] + z[3]);
        ss += (z[0]*z[0] + z[1]*z[1]) + (z[2]*z[2] + z[3]*z[3]);

        // Store z as fp16 (8B per thread-row). Warp covers full 128B lines ->
        // no read-for-ownership. Default caching: z should LIVE in L2 for pass2.
        __half2 h01 = __floats2half2_rn(z[0], z[1]);
        __half2 h23 = __floats2half2_rn(z[2], z[3]);
        float2 w;
        *reinterpret_cast<__half2*>(&w.x) = h01;
        *reinterpret_cast<__half2*>(&w.y) = h23;
        *(float2*)(zb + (size_t)(r0 + i) * WDIM + col) = w;
    }
}

__global__ void __launch_bounds__(256) ltpe_pass1(const float* __restrict__ x) {
    int strip = blockIdx.x & (STRIPS - 1);
    int img   = blockIdx.x >> 6;
    int r0    = strip * RSTRIP;
    const float* base = x + (size_t)img * HDIM * WDIM;
    __half* zb = g_z + (size_t)img * HDIM * WDIM;
    int col  = threadIdx.x * 4;
    int lane = threadIdx.x & 31;

    float s, ss;
    if (strip != 0 && strip != STRIPS - 1) pass1_strip<true >(base, zb, r0, col, lane, s, ss);
    else                                   pass1_strip<false>(base, zb, r0, col, lane, s, ss);

    #pragma unroll
    for (int o = 16; o > 0; o >>= 1) {
        s  += __shfl_xor_sync(0xffffffffu, s,  o);
        ss += __shfl_xor_sync(0xffffffffu, ss, o);
    }
    __shared__ float ws[8], wss[8];
    int wid = threadIdx.x >> 5;
    if (lane == 0) { ws[wid] = s; wss[wid] = ss; }
    __syncthreads();
    if (threadIdx.x == 0) {
        float S = 0.f, SS = 0.f;
        #pragma unroll
        for (int i = 0; i < 8; i++) { S += ws[i]; SS += wss[i]; }
        g_psum[blockIdx.x] = (double)S;
        g_pss [blockIdx.x] = (double)SS;
    }
}

// ============ Pass 2: read fp16 z (L2-hot), normalize, stream out ===========
__global__ void __launch_bounds__(256) ltpe_pass2(float* __restrict__ out) {
    // REVERSE order: read the most-recently-written z first (LRU-friendly).
    int bid   = (NBLOCKS - 1) - blockIdx.x;
    int strip = bid & (STRIPS - 1);
    int img   = bid >> 6;
    int r0    = strip * RSTRIP;
    int col   = threadIdx.x * 4;

    const __half* zb = g_z + (size_t)img * HDIM * WDIM;

    // Prefetch ALL 16 z-rows (8B each) BEFORE the stats reduce so the
    // L2/DRAM round-trips hide under it. 16 float2 = 32 regs.
    float2 zraw[RSTRIP];
    #pragma unroll
    for (int i = 0; i < RSTRIP; i++)
        zraw[i] = __ldlu((const float2*)(zb + (size_t)(r0 + i) * WDIM + col));

    // Fixed-order stats reduction (deterministic).
    __shared__ double rs[STRIPS], rss[STRIPS];
    __shared__ float s_mean, s_inv;
    if (threadIdx.x < STRIPS) {
        rs[threadIdx.x]  = g_psum[img * STRIPS + threadIdx.x];
        rss[threadIdx.x] = g_pss [img * STRIPS + threadIdx.x];
    }
    __syncthreads();
    #pragma unroll
    for (int o = STRIPS / 2; o > 0; o >>= 1) {
        if (threadIdx.x < o) {
            rs[threadIdx.x]  += rs[threadIdx.x + o];
            rss[threadIdx.x] += rss[threadIdx.x + o];
        }
        __syncthreads();
    }
    if (threadIdx.x == 0) {
        const double N = (double)HDIM * WDIM;
        double mm  = rs[0] / N;
        double var = rss[0] / N - mm * mm;
        s_mean = (float)mm;
        // o = 0.5*z + 0.5 with IN eps=1e-5  =>  normalize z with eps' = 4e-5
        s_inv = (float)rsqrt(var + 4e-5);
    }
    __syncthreads();
    const float m = s_mean, inv = s_inv;

    float* obase = out + (size_t)img * HDIM * WDIM;
    #pragma unroll
    for (int i = 0; i < RSTRIP; i++) {
        __half2 h01 = *reinterpret_cast<__half2*>(&zraw[i].x);
        __half2 h23 = *reinterpret_cast<__half2*>(&zraw[i].y);
        float2 f01 = __half22float2(h01);
        float2 f23 = __half22float2(h23);
        float4 o4;
        o4.x = (f01.x - m) * inv;
        o4.y = (f01.y - m) * inv;
        o4.z = (f23.x - m) * inv;
        o4.w = (f23.y - m) * inv;
        // Evict-first: output never re-read; don't displace z in L2.
        __stcs((float4*)(obase + (size_t)(r0 + i) * WDIM + col), o4);
    }
}

extern "C" void kernel_launch(void* const* d_in, const int* in_sizes, int n_in,
                              void* d_out, int out_size) {
    const float* x   = (const float*)d_in[0];
    float*       out = (float*)d_out;

    ltpe_pass1<<<NBLOCKS, 256>>>(x);
    ltpe_pass2<<<NBLOCKS, 256>>>(out);
}